// round 13
// baseline (speedup 1.0000x reference)
#include <cuda_runtime.h>
#include <cuda_bf16.h>
#include <math.h>

#define N_NODES 50000
#define N_EDGES 600000
#define DIM 128
#define NUM_CLASSES 10
#define EPSF 1e-15f
#define MAX_NORM (1.0f - 1e-5f)

#define NPT 25024                  // node-pair pitch (25000 pairs + pad)
#define FT_PITCH 129
#define MM_TILES ((N_NODES + 63) / 64)   // 782 tiles of 64 nodes
#define MM_GRID 444                       // 3 blocks/SM

#define CSR_BLOCKS 49
#define CSR_THREADS 1024

typedef unsigned long long u64;

// scratch (device globals: no allocation allowed)
__device__ float g_y[N_NODES * DIM];
__device__ float g_agg[N_NODES * DIM];
__device__ u64   g_xTn[DIM * NPT];       // xTn[k][np] = (t[k][2np], t[k][2np+1])
__device__ u64   g_Wd1[DIM * DIM];       // Wd[k*128+j] = (W[j][k], W[j][k])
__device__ u64   g_Wd2[DIM * DIM];
__device__ int   g_mult;
__device__ int   g_count[N_NODES];
__device__ int   g_cursor[N_NODES];
__device__ int   g_rowstart[N_NODES + 1];
__device__ int   g_bsum[CSR_BLOCKS];
__device__ volatile unsigned g_bar_gen;   // monotonic across graph replays
__device__ unsigned g_bar_cnt;            // self-resets
__device__ int   g_esrc[N_EDGES];

// ---------------------------------------------------------------------------
// packed fp32x2 helpers (Blackwell FFMA2 — PTX-only)
__device__ __forceinline__ u64 fma2(u64 a, u64 b, u64 c) {
    u64 d;
    asm("fma.rn.f32x2 %0, %1, %2, %3;" : "=l"(d) : "l"(a), "l"(b), "l"(c));
    return d;
}
__device__ __forceinline__ u64 add2(u64 a, u64 b) {
    u64 d;
    asm("add.rn.f32x2 %0, %1, %2;" : "=l"(d) : "l"(a), "l"(b));
    return d;
}
__device__ __forceinline__ u64 mul2(u64 a, u64 b) {
    u64 d;
    asm("mul.rn.f32x2 %0, %1, %2;" : "=l"(d) : "l"(a), "l"(b));
    return d;
}
__device__ __forceinline__ u64 pack2(float lo, float hi) {
    u64 r;
    asm("mov.b64 %0, {%1, %2};" : "=l"(r) : "f"(lo), "f"(hi));
    return r;
}
__device__ __forceinline__ void unpack2(u64 v, float& lo, float& hi) {
    asm("mov.b64 {%0, %1}, %2;" : "=f"(lo), "=f"(hi) : "l"(v));
}

// ---------------------------------------------------------------------------
// software grid barrier (all CSR_BLOCKS resident: 49 << 148 SMs)
__device__ __forceinline__ void grid_barrier() {
    __syncthreads();
    if (threadIdx.x == 0) {
        __threadfence();
        unsigned my = g_bar_gen;
        unsigned a = atomicAdd(&g_bar_cnt, 1);
        if (a == CSR_BLOCKS - 1) {
            g_bar_cnt = 0;
            __threadfence();
            g_bar_gen = my + 1;
        } else {
            while (g_bar_gen == my) __nanosleep(32);
        }
    }
    __syncthreads();
}

// ---------------------------------------------------------------------------
// Fused CSR build (side stream): detect + zero + hist + scan + bucket scatter.
__global__ void __launch_bounds__(CSR_THREADS)
csr_kernel(const int* __restrict__ e32) {
    const int b = blockIdx.x, t = threadIdx.x;
    const int gid = b * CSR_THREADS + t;
    const int nth = CSR_BLOCKS * CSR_THREADS;

    if (b == 0 && t < 32) {
        int v1 = e32[2 * t + 1];
        int bad = __any_sync(0xffffffffu, v1 != 0);
        if (t == 0) g_mult = bad ? 1 : 2;
    }
    if (gid < N_NODES) g_count[gid] = 0;
    grid_barrier();

    const int m = g_mult;
    for (int e = gid; e < N_EDGES; e += nth) {
        int dst = e32[(long long)(N_EDGES + e) * m];
        atomicAdd(&g_count[dst], 1);
    }
    grid_barrier();

    __shared__ int wsum[32];
    __shared__ int part[2];
    const int lane = t & 31, w = t >> 5;
    int v = (gid < N_NODES) ? g_count[gid] : 0;
    int x = v;
#pragma unroll
    for (int d = 1; d < 32; d <<= 1) {
        int y = __shfl_up_sync(0xffffffffu, x, d);
        if (lane >= d) x += y;
    }
    if (lane == 31) wsum[w] = x;
    __syncthreads();
    if (w == 0) {
        int s = wsum[lane];
#pragma unroll
        for (int d = 1; d < 32; d <<= 1) {
            int y = __shfl_up_sync(0xffffffffu, s, d);
            if (lane >= d) s += y;
        }
        wsum[lane] = s;
    }
    __syncthreads();
    int excl = x - v + (w ? wsum[w - 1] : 0);
    if (t == CSR_THREADS - 1) g_bsum[b] = excl + v;
    grid_barrier();

    if (t < 64) {
        int pv = (t < b) ? g_bsum[t] : 0;
#pragma unroll
        for (int d = 16; d > 0; d >>= 1)
            pv += __shfl_xor_sync(0xffffffffu, pv, d);
        if (lane == 0) part[w] = pv;
    }
    __syncthreads();
    const int boff = part[0] + part[1];
    if (gid < N_NODES) {
        int rv = excl + boff;
        g_rowstart[gid] = rv;
        g_cursor[gid] = rv;
    }
    if (gid == 0) g_rowstart[N_NODES] = N_EDGES;
    grid_barrier();

    for (int e = gid; e < N_EDGES; e += nth) {
        int src = e32[(long long)e * m];
        int dst = e32[(long long)(N_EDGES + e) * m];
        int pos = atomicAdd(&g_cursor[dst], 1);
        g_esrc[pos] = src;
    }
}

// ---------------------------------------------------------------------------
// wprep: Wd[k*128 + j] = (W[j][k], W[j][k])  (transposed + duplicated)
__global__ void __launch_bounds__(256)
wprep_kernel(const float* __restrict__ W1, const float* __restrict__ W2,
             u64* __restrict__ Wd1, u64* __restrict__ Wd2) {
    __shared__ float s[32 * FT_PITCH];
    const int mtx = blockIdx.x >> 2;
    const int j0 = (blockIdx.x & 3) * 32;
    const float* W = mtx ? W2 : W1;
    u64* Wd = mtx ? Wd2 : Wd1;
    const int tid = threadIdx.x;

#pragma unroll
    for (int q = 0; q < 4; q++) {
        int idx = q * 256 + tid;          // 0..1023 float4s
        int jj = idx >> 5, k4 = idx & 31;
        float4 v = __ldg((const float4*)&W[(j0 + jj) * DIM + k4 * 4]);
        float* sr = &s[jj * FT_PITCH + k4 * 4];
        sr[0] = v.x; sr[1] = v.y; sr[2] = v.z; sr[3] = v.w;
    }
    __syncthreads();
#pragma unroll
    for (int q = 0; q < 16; q++) {
        int idx = q * 256 + tid;          // 0..4095
        int k = idx >> 5, jj = idx & 31;
        float v = s[jj * FT_PITCH + k];
        Wd[k * DIM + j0 + jj] = pack2(v, v);
    }
}

// ---------------------------------------------------------------------------
// facT: 32-node tile -> (optional logmap0 factor) -> node-paired transposed write:
// xTn[k][np] = (fac*in[2np][k], fac*in[2np+1][k])
__global__ void __launch_bounds__(256)
facT_kernel(const float* __restrict__ in, u64* __restrict__ xTn, int do_norm) {
    __shared__ float s[32 * FT_PITCH];
    __shared__ float facs[32];
    const int tid = threadIdx.x, lane = tid & 31, w = tid >> 5;
    const int node0 = blockIdx.x * 32;

#pragma unroll
    for (int q = 0; q < 4; q++) {
        int idx = q * 256 + tid;
        int n = idx >> 5, c4 = idx & 31;
        float4 v = make_float4(0.f, 0.f, 0.f, 0.f);
        if (node0 + n < N_NODES)
            v = __ldg((const float4*)&in[(node0 + n) * DIM + c4 * 4]);
        float* sr = &s[n * FT_PITCH + c4 * 4];
        sr[0] = v.x; sr[1] = v.y; sr[2] = v.z; sr[3] = v.w;
    }
    __syncthreads();

    if (do_norm) {
#pragma unroll
        for (int j = 0; j < 4; j++) {
            int n = w * 4 + j;
            const float* sr = &s[n * FT_PITCH];
            float a0 = sr[lane], a1 = sr[lane + 32];
            float a2 = sr[lane + 64], a3 = sr[lane + 96];
            float ss = a0 * a0 + a1 * a1 + a2 * a2 + a3 * a3;
            ss += __shfl_xor_sync(0xffffffff, ss, 16);
            ss += __shfl_xor_sync(0xffffffff, ss, 8);
            ss += __shfl_xor_sync(0xffffffff, ss, 4);
            ss += __shfl_xor_sync(0xffffffff, ss, 2);
            ss += __shfl_xor_sync(0xffffffff, ss, 1);
            if (lane == 0) {
                float nn = fmaxf(sqrtf(ss), EPSF);
                facs[n] = atanhf(fminf(nn, MAX_NORM)) / nn;
            }
        }
    } else {
        if (tid < 32) facs[tid] = 1.0f;
    }
    __syncthreads();

    const int np0 = node0 >> 1;
#pragma unroll
    for (int q = 0; q < 8; q++) {
        int idx = q * 256 + tid;          // 0..2047
        int k = idx >> 4, i = idx & 15;   // k row, node-pair within tile
        float vlo = facs[2 * i]     * s[(2 * i) * FT_PITCH + k];
        float vhi = facs[2 * i + 1] * s[(2 * i + 1) * FT_PITCH + k];
        xTn[k * NPT + np0 + i] = pack2(vlo, vhi);
    }
}

// ---------------------------------------------------------------------------
// mm: y = expmap0( t @ W^T + b ). Node-paired T/acc; W pre-duplicated in gmem
// (L1-resident, block-wide reuse). smem = Tsh only (32KB) -> 3 blocks/SM.
// Thread: cols {lane,+32,+64,+96} x 4 node-pairs (8 nodes). acc = 16 u64.
__global__ void __launch_bounds__(256, 3)
mm_kernel(const u64* __restrict__ xTn, const u64* __restrict__ Wd,
          const float* __restrict__ bias, float* __restrict__ y) {
    __shared__ u64 Tsh[DIM * 32];   // [k][np], 32KB static

    const int tid = threadIdx.x, lane = tid & 31, w = tid >> 5;

    const float b0 = __ldg(&bias[lane]);
    const float b1 = __ldg(&bias[lane + 32]);
    const float b2 = __ldg(&bias[lane + 64]);
    const float b3 = __ldg(&bias[lane + 96]);
    const u64 bd0 = pack2(b0, b0), bd1 = pack2(b1, b1);
    const u64 bd2 = pack2(b2, b2), bd3 = pack2(b3, b3);

    for (int tile = blockIdx.x; tile < MM_TILES; tile += gridDim.x) {
        const int np0 = tile * 32;
        const int n0 = tile * 64;

        // stage Tsh (coalesced 16B copies)
#pragma unroll
        for (int q = 0; q < 8; q++) {
            int idx = q * 256 + tid;            // 0..2047 ulonglong2
            int k = idx >> 4, c2 = idx & 15;
            *(ulonglong2*)&Tsh[k * 32 + c2 * 2] =
                *(const ulonglong2*)&xTn[k * NPT + np0 + c2 * 2];
        }
        __syncthreads();

        u64 acc[4][4];
#pragma unroll
        for (int c = 0; c < 4; c++)
#pragma unroll
            for (int p = 0; p < 4; p++) acc[c][p] = 0ULL;

#pragma unroll 2
        for (int k = 0; k < DIM; k++) {
            const u64* wr = &Wd[k * DIM + lane];
            u64 w0 = __ldg(wr);
            u64 w1 = __ldg(wr + 32);
            u64 w2 = __ldg(wr + 64);
            u64 w3 = __ldg(wr + 96);
            const ulonglong2* tp = (const ulonglong2*)&Tsh[k * 32 + 4 * w];
            ulonglong2 t0 = tp[0], t1 = tp[1];
            acc[0][0] = fma2(w0, t0.x, acc[0][0]);
            acc[1][0] = fma2(w1, t0.x, acc[1][0]);
            acc[2][0] = fma2(w2, t0.x, acc[2][0]);
            acc[3][0] = fma2(w3, t0.x, acc[3][0]);
            acc[0][1] = fma2(w0, t0.y, acc[0][1]);
            acc[1][1] = fma2(w1, t0.y, acc[1][1]);
            acc[2][1] = fma2(w2, t0.y, acc[2][1]);
            acc[3][1] = fma2(w3, t0.y, acc[3][1]);
            acc[0][2] = fma2(w0, t1.x, acc[0][2]);
            acc[1][2] = fma2(w1, t1.x, acc[1][2]);
            acc[2][2] = fma2(w2, t1.x, acc[2][2]);
            acc[3][2] = fma2(w3, t1.x, acc[3][2]);
            acc[0][3] = fma2(w0, t1.y, acc[0][3]);
            acc[1][3] = fma2(w1, t1.y, acc[1][3]);
            acc[2][3] = fma2(w2, t1.y, acc[2][3]);
            acc[3][3] = fma2(w3, t1.y, acc[3][3]);
        }

        // epilogue: +bias, packed norm reduction (2 nodes at once), expmap0, store
#pragma unroll
        for (int p = 0; p < 4; p++) {
            u64 h0 = add2(acc[0][p], bd0);
            u64 h1 = add2(acc[1][p], bd1);
            u64 h2 = add2(acc[2][p], bd2);
            u64 h3 = add2(acc[3][p], bd3);
            u64 ss = fma2(h0, h0, fma2(h1, h1, fma2(h2, h2, mul2(h3, h3))));
#pragma unroll
            for (int d = 16; d > 0; d >>= 1)
                ss = add2(ss, __shfl_xor_sync(0xffffffffu, ss, d));
            float sl, sh;
            unpack2(ss, sl, sh);
            float nl = fmaxf(sqrtf(sl), EPSF);
            float nh = fmaxf(sqrtf(sh), EPSF);
            u64 fp = pack2(tanhf(nl) / nl, tanhf(nh) / nh);
            u64 m0 = mul2(fp, h0), m1 = mul2(fp, h1);
            u64 m2 = mul2(fp, h2), m3 = mul2(fp, h3);
            float l0, u0v, l1, u1v, l2, u2v, l3, u3v;
            unpack2(m0, l0, u0v); unpack2(m1, l1, u1v);
            unpack2(m2, l2, u2v); unpack2(m3, l3, u3v);
            int nA = n0 + 8 * w + 2 * p;
            if (nA < N_NODES) {
                float* yr = &y[nA * DIM + lane];
                yr[0] = l0; yr[32] = l1; yr[64] = l2; yr[96] = l3;
            }
            if (nA + 1 < N_NODES) {
                float* yr = &y[(nA + 1) * DIM + lane];
                yr[0] = u0v; yr[32] = u1v; yr[64] = u2v; yr[96] = u3v;
            }
        }
        __syncthreads();
    }
}

// ---------------------------------------------------------------------------
// Warp-level CSR row gather, 8-deep MLP. Returns per-lane float4 sum.
__device__ __forceinline__ float4 gather_row(const int* __restrict__ esrc,
                                             const float* __restrict__ y,
                                             int s, int e, int lane4) {
    float4 a0 = make_float4(0.f, 0.f, 0.f, 0.f);
    float4 a1 = make_float4(0.f, 0.f, 0.f, 0.f);
    float4 a2 = make_float4(0.f, 0.f, 0.f, 0.f);
    float4 a3 = make_float4(0.f, 0.f, 0.f, 0.f);
    int i = s;
    for (; i + 8 <= e; i += 8) {
        int s0 = __ldg(&esrc[i + 0]);
        int s1 = __ldg(&esrc[i + 1]);
        int s2 = __ldg(&esrc[i + 2]);
        int s3 = __ldg(&esrc[i + 3]);
        int s4 = __ldg(&esrc[i + 4]);
        int s5 = __ldg(&esrc[i + 5]);
        int s6 = __ldg(&esrc[i + 6]);
        int s7 = __ldg(&esrc[i + 7]);
        float4 v0 = __ldg((const float4*)&y[s0 * DIM + lane4]);
        float4 v1 = __ldg((const float4*)&y[s1 * DIM + lane4]);
        float4 v2 = __ldg((const float4*)&y[s2 * DIM + lane4]);
        float4 v3 = __ldg((const float4*)&y[s3 * DIM + lane4]);
        float4 v4 = __ldg((const float4*)&y[s4 * DIM + lane4]);
        float4 v5 = __ldg((const float4*)&y[s5 * DIM + lane4]);
        float4 v6 = __ldg((const float4*)&y[s6 * DIM + lane4]);
        float4 v7 = __ldg((const float4*)&y[s7 * DIM + lane4]);
        a0.x += v0.x; a0.y += v0.y; a0.z += v0.z; a0.w += v0.w;
        a1.x += v1.x; a1.y += v1.y; a1.z += v1.z; a1.w += v1.w;
        a2.x += v2.x; a2.y += v2.y; a2.z += v2.z; a2.w += v2.w;
        a3.x += v3.x; a3.y += v3.y; a3.z += v3.z; a3.w += v3.w;
        a0.x += v4.x; a0.y += v4.y; a0.z += v4.z; a0.w += v4.w;
        a1.x += v5.x; a1.y += v5.y; a1.z += v5.z; a1.w += v5.w;
        a2.x += v6.x; a2.y += v6.y; a2.z += v6.z; a2.w += v6.w;
        a3.x += v7.x; a3.y += v7.y; a3.z += v7.z; a3.w += v7.w;
    }
    for (; i + 2 <= e; i += 2) {
        int s0 = __ldg(&esrc[i + 0]);
        int s1 = __ldg(&esrc[i + 1]);
        float4 v0 = __ldg((const float4*)&y[s0 * DIM + lane4]);
        float4 v1 = __ldg((const float4*)&y[s1 * DIM + lane4]);
        a0.x += v0.x; a0.y += v0.y; a0.z += v0.z; a0.w += v0.w;
        a1.x += v1.x; a1.y += v1.y; a1.z += v1.z; a1.w += v1.w;
    }
    if (i < e) {
        int s0 = __ldg(&esrc[i]);
        float4 v0 = __ldg((const float4*)&y[s0 * DIM + lane4]);
        a2.x += v0.x; a2.y += v0.y; a2.z += v0.z; a2.w += v0.w;
    }
    float4 r;
    r.x = (a0.x + a1.x) + (a2.x + a3.x);
    r.y = (a0.y + a1.y) + (a2.y + a3.y);
    r.z = (a0.z + a1.z) + (a2.z + a3.z);
    r.w = (a0.w + a1.w) + (a2.w + a3.w);
    return r;
}

// Layer-1 aggregation fused with relu + logmap0 scaling.
__global__ void __launch_bounds__(256)
gather_kernel(const int* __restrict__ esrc, const int* __restrict__ rs,
              const float* __restrict__ y, float* __restrict__ agg) {
    const int lane = threadIdx.x & 31;
    const int wid  = threadIdx.x >> 5;
    const int node = blockIdx.x * (blockDim.x >> 5) + wid;
    if (node >= N_NODES) return;
    const int s = rs[node];
    const int e = rs[node + 1];
    float4 r = gather_row(esrc, y, s, e, lane * 4);

    r.x = fmaxf(r.x, 0.f); r.y = fmaxf(r.y, 0.f);
    r.z = fmaxf(r.z, 0.f); r.w = fmaxf(r.w, 0.f);

    float ss = r.x * r.x + r.y * r.y + r.z * r.z + r.w * r.w;
    ss += __shfl_xor_sync(0xffffffff, ss, 16);
    ss += __shfl_xor_sync(0xffffffff, ss, 8);
    ss += __shfl_xor_sync(0xffffffff, ss, 4);
    ss += __shfl_xor_sync(0xffffffff, ss, 2);
    ss += __shfl_xor_sync(0xffffffff, ss, 1);
    float n = fmaxf(sqrtf(ss), EPSF);
    float f = atanhf(fminf(n, MAX_NORM)) / n;

    float4 o = make_float4(f * r.x, f * r.y, f * r.z, f * r.w);
    *(float4*)&agg[node * DIM + lane * 4] = o;
}

// Layer-2 aggregation fused with classifier.
__global__ void __launch_bounds__(256)
gather_cls_kernel(const int* __restrict__ esrc, const int* __restrict__ rs,
                  const float* __restrict__ y, const float* __restrict__ Wc,
                  const float* __restrict__ bc, float* __restrict__ out) {
    __shared__ float Wcs[NUM_CLASSES * DIM];
    __shared__ float bcs[NUM_CLASSES];
    const int tid = threadIdx.x;
    for (int i = tid; i < NUM_CLASSES * DIM; i += blockDim.x) Wcs[i] = Wc[i];
    if (tid < NUM_CLASSES) bcs[tid] = bc[tid];
    __syncthreads();

    const int lane = tid & 31;
    const int wid  = tid >> 5;
    const int node = blockIdx.x * (blockDim.x >> 5) + wid;
    if (node >= N_NODES) return;

    const int s = rs[node];
    const int e = rs[node + 1];
    float4 h = gather_row(esrc, y, s, e, lane * 4);

    h.x = fmaxf(h.x, 0.f); h.y = fmaxf(h.y, 0.f);
    h.z = fmaxf(h.z, 0.f); h.w = fmaxf(h.w, 0.f);

    float sq = h.x * h.x + h.y * h.y + h.z * h.z + h.w * h.w;
    sq += __shfl_xor_sync(0xffffffff, sq, 16);
    sq += __shfl_xor_sync(0xffffffff, sq, 8);
    sq += __shfl_xor_sync(0xffffffff, sq, 4);
    sq += __shfl_xor_sync(0xffffffff, sq, 2);
    sq += __shfl_xor_sync(0xffffffff, sq, 1);
    float n = fmaxf(sqrtf(sq), EPSF);
    float f = atanhf(fminf(n, MAX_NORM)) / n;
    float4 t = make_float4(f * h.x, f * h.y, f * h.z, f * h.w);

#pragma unroll
    for (int c = 0; c < NUM_CLASSES; c++) {
        float4 w = *(const float4*)&Wcs[c * DIM + lane * 4];
        float p = t.x * w.x + t.y * w.y + t.z * w.z + t.w * w.w;
        p += __shfl_xor_sync(0xffffffff, p, 16);
        p += __shfl_xor_sync(0xffffffff, p, 8);
        p += __shfl_xor_sync(0xffffffff, p, 4);
        p += __shfl_xor_sync(0xffffffff, p, 2);
        p += __shfl_xor_sync(0xffffffff, p, 1);
        if (lane == 0) out[node * NUM_CLASSES + c] = p + bcs[c];
    }
}

// ---------------------------------------------------------------------------
extern "C" void kernel_launch(void* const* d_in, const int* in_sizes, int n_in,
                              void* d_out, int out_size) {
    const int*   e32 = (const int*)d_in[0];
    const float* x   = (const float*)d_in[1];
    const float* W1  = (const float*)d_in[2];
    const float* b1  = (const float*)d_in[3];
    const float* W2  = (const float*)d_in[4];
    const float* b2  = (const float*)d_in[5];
    const float* Wc  = (const float*)d_in[6];
    const float* bc  = (const float*)d_in[7];
    float* out = (float*)d_out;

    float *y, *agg;
    u64 *xTn, *Wd1, *Wd2;
    int *rs, *es;
    cudaGetSymbolAddress((void**)&y,   g_y);
    cudaGetSymbolAddress((void**)&agg, g_agg);
    cudaGetSymbolAddress((void**)&xTn, g_xTn);
    cudaGetSymbolAddress((void**)&Wd1, g_Wd1);
    cudaGetSymbolAddress((void**)&Wd2, g_Wd2);
    cudaGetSymbolAddress((void**)&rs,  g_rowstart);
    cudaGetSymbolAddress((void**)&es,  g_esrc);

    // one-time host resources (no device memory involved)
    static cudaStream_t s2 = nullptr;
    static cudaEvent_t evF = nullptr, evW = nullptr, evC = nullptr;
    static bool init_done = false;
    if (!init_done) {
        init_done = true;
        cudaStreamCreateWithFlags(&s2, cudaStreamNonBlocking);
        cudaEventCreateWithFlags(&evF, cudaEventDisableTiming);
        cudaEventCreateWithFlags(&evW, cudaEventDisableTiming);
        cudaEventCreateWithFlags(&evC, cudaEventDisableTiming);
    }

    const int ftblocks = (N_NODES + 31) / 32;   // 1563
    const int gblocks  = (N_NODES + 7) / 8;

    // fork side stream: W prep + CSR build overlap layer-1 transform
    cudaEventRecord(evF, 0);
    cudaStreamWaitEvent(s2, evF, 0);
    wprep_kernel<<<8, 256, 0, s2>>>(W1, W2, Wd1, Wd2);
    cudaEventRecord(evW, s2);
    csr_kernel<<<CSR_BLOCKS, CSR_THREADS, 0, s2>>>(e32);
    cudaEventRecord(evC, s2);

    // main stream
    facT_kernel<<<ftblocks, 256>>>(x, xTn, 1);
    cudaStreamWaitEvent(0, evW, 0);                    // mm1 needs Wd1
    mm_kernel<<<MM_GRID, 256>>>(xTn, Wd1, b1, y);
    cudaStreamWaitEvent(0, evC, 0);                    // gather needs CSR
    gather_kernel<<<gblocks, 256>>>(es, rs, y, agg);   // + relu + logmap0
    facT_kernel<<<ftblocks, 256>>>(agg, xTn, 0);       // pure transpose
    mm_kernel<<<MM_GRID, 256>>>(xTn, Wd2, b2, y);
    gather_cls_kernel<<<gblocks, 256>>>(es, rs, y, Wc, bc, out);
}

// round 15
// speedup vs baseline: 1.2575x; 1.2575x over previous
#include <cuda_runtime.h>
#include <cuda_bf16.h>
#include <math.h>

#define N_NODES 50000
#define N_EDGES 600000
#define DIM 128
#define NUM_CLASSES 10
#define EPSF 1e-15f
#define MAX_NORM (1.0f - 1e-5f)

#define KP 64                      // k-pairs
#define XTP 50048                  // node pitch for pair-packed xT
#define FT_PITCH 129
#define MM_TILES ((N_NODES + 63) / 64)   // 782
#define MM_GRID 296
#define MM_SMEM ((KP * DIM + KP * 64) * 8)   // Wsh 64KB + Tsh 32KB = 96KB

#define CSR_BLOCKS 49
#define CSR_THREADS 1024

typedef unsigned long long u64;

// scratch (device globals: no allocation allowed)
__device__ float g_y[N_NODES * DIM];
__device__ u64   g_xTp[KP * XTP];        // (t[2kp][n], t[2kp+1][n])
__device__ u64   g_Wp1[KP * DIM];        // (W[j][2kp], W[j][2kp+1]) at [kp*128+j]
__device__ u64   g_Wp2[KP * DIM];
__device__ int   g_mult;
__device__ int   g_count[N_NODES];
__device__ int   g_cursor[N_NODES];
__device__ int   g_rowstart[N_NODES + 1];
__device__ int   g_bsum[CSR_BLOCKS];
__device__ volatile unsigned g_bar_gen;   // monotonic across graph replays
__device__ unsigned g_bar_cnt;            // self-resets
__device__ int   g_esrc[N_EDGES];

// ---------------------------------------------------------------------------
// packed fp32x2 helpers (Blackwell FFMA2 — PTX-only)
__device__ __forceinline__ u64 fma2(u64 a, u64 b, u64 c) {
    u64 d;
    asm("fma.rn.f32x2 %0, %1, %2, %3;" : "=l"(d) : "l"(a), "l"(b), "l"(c));
    return d;
}
__device__ __forceinline__ u64 pack2(float lo, float hi) {
    u64 r;
    asm("mov.b64 %0, {%1, %2};" : "=l"(r) : "f"(lo), "f"(hi));
    return r;
}
__device__ __forceinline__ void unpack2(u64 v, float& lo, float& hi) {
    asm("mov.b64 {%0, %1}, %2;" : "=f"(lo), "=f"(hi) : "l"(v));
}
__device__ __forceinline__ float sum2(u64 v) {
    float lo, hi;
    unpack2(v, lo, hi);
    return lo + hi;
}

// ---------------------------------------------------------------------------
// software grid barrier (all CSR_BLOCKS resident: 49 << 148 SMs)
__device__ __forceinline__ void grid_barrier() {
    __syncthreads();
    if (threadIdx.x == 0) {
        __threadfence();
        unsigned my = g_bar_gen;
        unsigned a = atomicAdd(&g_bar_cnt, 1);
        if (a == CSR_BLOCKS - 1) {
            g_bar_cnt = 0;
            __threadfence();
            g_bar_gen = my + 1;
        } else {
            while (g_bar_gen == my) __nanosleep(32);
        }
    }
    __syncthreads();
}

// ---------------------------------------------------------------------------
// Fused CSR build (side stream): detect + zero + hist + scan + bucket scatter.
__global__ void __launch_bounds__(CSR_THREADS)
csr_kernel(const int* __restrict__ e32) {
    const int b = blockIdx.x, t = threadIdx.x;
    const int gid = b * CSR_THREADS + t;
    const int nth = CSR_BLOCKS * CSR_THREADS;

    if (b == 0 && t < 32) {
        int v1 = e32[2 * t + 1];
        int bad = __any_sync(0xffffffffu, v1 != 0);
        if (t == 0) g_mult = bad ? 1 : 2;
    }
    if (gid < N_NODES) g_count[gid] = 0;
    grid_barrier();

    const int m = g_mult;
    for (int e = gid; e < N_EDGES; e += nth) {
        int dst = e32[(long long)(N_EDGES + e) * m];
        atomicAdd(&g_count[dst], 1);
    }
    grid_barrier();

    __shared__ int wsum[32];
    __shared__ int part[2];
    const int lane = t & 31, w = t >> 5;
    int v = (gid < N_NODES) ? g_count[gid] : 0;
    int x = v;
#pragma unroll
    for (int d = 1; d < 32; d <<= 1) {
        int y = __shfl_up_sync(0xffffffffu, x, d);
        if (lane >= d) x += y;
    }
    if (lane == 31) wsum[w] = x;
    __syncthreads();
    if (w == 0) {
        int s = wsum[lane];
#pragma unroll
        for (int d = 1; d < 32; d <<= 1) {
            int y = __shfl_up_sync(0xffffffffu, s, d);
            if (lane >= d) s += y;
        }
        wsum[lane] = s;
    }
    __syncthreads();
    int excl = x - v + (w ? wsum[w - 1] : 0);
    if (t == CSR_THREADS - 1) g_bsum[b] = excl + v;
    grid_barrier();

    if (t < 64) {
        int pv = (t < b) ? g_bsum[t] : 0;
#pragma unroll
        for (int d = 16; d > 0; d >>= 1)
            pv += __shfl_xor_sync(0xffffffffu, pv, d);
        if (lane == 0) part[w] = pv;
    }
    __syncthreads();
    const int boff = part[0] + part[1];
    if (gid < N_NODES) {
        int rv = excl + boff;
        g_rowstart[gid] = rv;
        g_cursor[gid] = rv;
    }
    if (gid == 0) g_rowstart[N_NODES] = N_EDGES;
    grid_barrier();

    for (int e = gid; e < N_EDGES; e += nth) {
        int src = e32[(long long)e * m];
        int dst = e32[(long long)(N_EDGES + e) * m];
        int pos = atomicAdd(&g_cursor[dst], 1);
        g_esrc[pos] = src;
    }
}

// ---------------------------------------------------------------------------
// wprep: transpose W1,W2 into k-pair layout Wp[kp*128 + j] = (W[j][2kp], W[j][2kp+1])
__global__ void __launch_bounds__(256)
wprep_kernel(const float* __restrict__ W1, const float* __restrict__ W2,
             u64* __restrict__ Wp1, u64* __restrict__ Wp2) {
    __shared__ float s[32 * FT_PITCH];
    const int mtx = blockIdx.x >> 2;
    const int j0 = (blockIdx.x & 3) * 32;
    const float* W = mtx ? W2 : W1;
    u64* Wp = mtx ? Wp2 : Wp1;
    const int tid = threadIdx.x;

#pragma unroll
    for (int q = 0; q < 4; q++) {
        int idx = q * 256 + tid;          // 0..1023 float4s
        int jj = idx >> 5, k4 = idx & 31;
        float4 v = __ldg((const float4*)&W[(j0 + jj) * DIM + k4 * 4]);
        float* sr = &s[jj * FT_PITCH + k4 * 4];
        sr[0] = v.x; sr[1] = v.y; sr[2] = v.z; sr[3] = v.w;
    }
    __syncthreads();
#pragma unroll
    for (int q = 0; q < 8; q++) {
        int idx = q * 256 + tid;          // 0..2047
        int kp = idx >> 5, jj = idx & 31;
        Wp[kp * DIM + j0 + jj] =
            pack2(s[jj * FT_PITCH + 2 * kp], s[jj * FT_PITCH + 2 * kp + 1]);
    }
}

// ---------------------------------------------------------------------------
// facT: 32-node tile -> logmap0 factor -> k-pair transposed write (layer 1 only).
__global__ void __launch_bounds__(256)
facT_kernel(const float* __restrict__ in, u64* __restrict__ xTp) {
    __shared__ float s[32 * FT_PITCH];
    __shared__ float facs[32];
    const int tid = threadIdx.x, lane = tid & 31, w = tid >> 5;
    const int node0 = blockIdx.x * 32;

#pragma unroll
    for (int q = 0; q < 4; q++) {
        int idx = q * 256 + tid;
        int n = idx >> 5, c4 = idx & 31;
        float4 v = make_float4(0.f, 0.f, 0.f, 0.f);
        if (node0 + n < N_NODES)
            v = __ldg((const float4*)&in[(node0 + n) * DIM + c4 * 4]);
        float* sr = &s[n * FT_PITCH + c4 * 4];
        sr[0] = v.x; sr[1] = v.y; sr[2] = v.z; sr[3] = v.w;
    }
    __syncthreads();

#pragma unroll
    for (int j = 0; j < 4; j++) {
        int n = w * 4 + j;
        const float* sr = &s[n * FT_PITCH];
        float a0 = sr[lane], a1 = sr[lane + 32];
        float a2 = sr[lane + 64], a3 = sr[lane + 96];
        float ss = a0 * a0 + a1 * a1 + a2 * a2 + a3 * a3;
        ss += __shfl_xor_sync(0xffffffff, ss, 16);
        ss += __shfl_xor_sync(0xffffffff, ss, 8);
        ss += __shfl_xor_sync(0xffffffff, ss, 4);
        ss += __shfl_xor_sync(0xffffffff, ss, 2);
        ss += __shfl_xor_sync(0xffffffff, ss, 1);
        if (lane == 0) {
            float nn = fmaxf(sqrtf(ss), EPSF);
            facs[n] = atanhf(fminf(nn, MAX_NORM)) / nn;
        }
    }
    __syncthreads();

    const int n = node0 + lane;
    const bool ok = n < N_NODES;
    const float fl = facs[lane];
#pragma unroll
    for (int i = 0; i < 8; i++) {
        int kp = w + 8 * i;
        float vlo = fl * s[lane * FT_PITCH + 2 * kp];
        float vhi = fl * s[lane * FT_PITCH + 2 * kp + 1];
        if (ok) xTp[kp * XTP + n] = pack2(vlo, vhi);
    }
}

// ---------------------------------------------------------------------------
// mm: y = expmap0( t @ W^T + b ). k-pair packed operands; round-9 proven
// version (unroll-2, ptxas-scheduled; W in smem, conflict-free column map).
__global__ void __launch_bounds__(256, 2)
mm_kernel(const u64* __restrict__ xTp, const u64* __restrict__ Wp,
          const float* __restrict__ bias, float* __restrict__ y) {
    extern __shared__ u64 sm8[];
    u64* Wsh = sm8;                // [kp][j], 64x128
    u64* Tsh = sm8 + KP * DIM;     // [kp][n], 64x64

    const int tid = threadIdx.x, lane = tid & 31, w = tid >> 5;

    {
        const ulonglong2* wg = (const ulonglong2*)Wp;
        ulonglong2* ws = (ulonglong2*)Wsh;
        for (int i = tid; i < KP * DIM / 2; i += 256) ws[i] = wg[i];
    }
    const float b0 = __ldg(&bias[lane]);
    const float b1 = __ldg(&bias[lane + 32]);
    const float b2 = __ldg(&bias[lane + 64]);
    const float b3 = __ldg(&bias[lane + 96]);
    __syncthreads();

    for (int tile = blockIdx.x; tile < MM_TILES; tile += gridDim.x) {
        const int n0 = tile * 64;

        // stage Tsh (coalesced ulonglong2 copies)
#pragma unroll
        for (int q = 0; q < 8; q++) {
            int idx = q * 256 + tid;            // 0..2047 ulonglong2
            int kp = idx >> 5, c2 = idx & 31;
            *(ulonglong2*)&Tsh[kp * 64 + c2 * 2] =
                *(const ulonglong2*)&xTp[kp * XTP + n0 + c2 * 2];
        }
        __syncthreads();

        u64 acc[4][8];
#pragma unroll
        for (int c = 0; c < 4; c++)
#pragma unroll
            for (int p = 0; p < 8; p++) acc[c][p] = 0ULL;

#pragma unroll 2
        for (int kp = 0; kp < KP; kp++) {
            const u64* wrow = &Wsh[kp * DIM + lane];
            u64 w0 = wrow[0];
            u64 w1 = wrow[32];
            u64 w2 = wrow[64];
            u64 w3 = wrow[96];
            const ulonglong2* tp = (const ulonglong2*)&Tsh[kp * 64 + 8 * w];
            ulonglong2 t0 = tp[0], t1 = tp[1], t2 = tp[2], t3 = tp[3];
            acc[0][0] = fma2(w0, t0.x, acc[0][0]);
            acc[1][0] = fma2(w1, t0.x, acc[1][0]);
            acc[2][0] = fma2(w2, t0.x, acc[2][0]);
            acc[3][0] = fma2(w3, t0.x, acc[3][0]);
            acc[0][1] = fma2(w0, t0.y, acc[0][1]);
            acc[1][1] = fma2(w1, t0.y, acc[1][1]);
            acc[2][1] = fma2(w2, t0.y, acc[2][1]);
            acc[3][1] = fma2(w3, t0.y, acc[3][1]);
            acc[0][2] = fma2(w0, t1.x, acc[0][2]);
            acc[1][2] = fma2(w1, t1.x, acc[1][2]);
            acc[2][2] = fma2(w2, t1.x, acc[2][2]);
            acc[3][2] = fma2(w3, t1.x, acc[3][2]);
            acc[0][3] = fma2(w0, t1.y, acc[0][3]);
            acc[1][3] = fma2(w1, t1.y, acc[1][3]);
            acc[2][3] = fma2(w2, t1.y, acc[2][3]);
            acc[3][3] = fma2(w3, t1.y, acc[3][3]);
            acc[0][4] = fma2(w0, t2.x, acc[0][4]);
            acc[1][4] = fma2(w1, t2.x, acc[1][4]);
            acc[2][4] = fma2(w2, t2.x, acc[2][4]);
            acc[3][4] = fma2(w3, t2.x, acc[3][4]);
            acc[0][5] = fma2(w0, t2.y, acc[0][5]);
            acc[1][5] = fma2(w1, t2.y, acc[1][5]);
            acc[2][5] = fma2(w2, t2.y, acc[2][5]);
            acc[3][5] = fma2(w3, t2.y, acc[3][5]);
            acc[0][6] = fma2(w0, t3.x, acc[0][6]);
            acc[1][6] = fma2(w1, t3.x, acc[1][6]);
            acc[2][6] = fma2(w2, t3.x, acc[2][6]);
            acc[3][6] = fma2(w3, t3.x, acc[3][6]);
            acc[0][7] = fma2(w0, t3.y, acc[0][7]);
            acc[1][7] = fma2(w1, t3.y, acc[1][7]);
            acc[2][7] = fma2(w2, t3.y, acc[2][7]);
            acc[3][7] = fma2(w3, t3.y, acc[3][7]);
        }

        // epilogue: collapse k-halves, +bias, expmap0, store (4 coalesced STG.32)
#pragma unroll
        for (int p = 0; p < 8; p++) {
            float h0 = sum2(acc[0][p]) + b0;
            float h1 = sum2(acc[1][p]) + b1;
            float h2 = sum2(acc[2][p]) + b2;
            float h3 = sum2(acc[3][p]) + b3;
            float ss = h0 * h0 + h1 * h1 + h2 * h2 + h3 * h3;
            ss += __shfl_xor_sync(0xffffffff, ss, 16);
            ss += __shfl_xor_sync(0xffffffff, ss, 8);
            ss += __shfl_xor_sync(0xffffffff, ss, 4);
            ss += __shfl_xor_sync(0xffffffff, ss, 2);
            ss += __shfl_xor_sync(0xffffffff, ss, 1);
            float nn = fmaxf(sqrtf(ss), EPSF);
            float f = tanhf(nn) / nn;
            int node = n0 + 8 * w + p;
            if (node < N_NODES) {
                float* yr = &y[node * DIM + lane];
                yr[0]  = f * h0;
                yr[32] = f * h1;
                yr[64] = f * h2;
                yr[96] = f * h3;
            }
        }
        __syncthreads();
    }
}

// ---------------------------------------------------------------------------
// Warp-level CSR row gather, 8-deep MLP. Returns per-lane float4 sum.
__device__ __forceinline__ float4 gather_row(const int* __restrict__ esrc,
                                             const float* __restrict__ y,
                                             int s, int e, int lane4) {
    float4 a0 = make_float4(0.f, 0.f, 0.f, 0.f);
    float4 a1 = make_float4(0.f, 0.f, 0.f, 0.f);
    float4 a2 = make_float4(0.f, 0.f, 0.f, 0.f);
    float4 a3 = make_float4(0.f, 0.f, 0.f, 0.f);
    int i = s;
    for (; i + 8 <= e; i += 8) {
        int s0 = __ldg(&esrc[i + 0]);
        int s1 = __ldg(&esrc[i + 1]);
        int s2 = __ldg(&esrc[i + 2]);
        int s3 = __ldg(&esrc[i + 3]);
        int s4 = __ldg(&esrc[i + 4]);
        int s5 = __ldg(&esrc[i + 5]);
        int s6 = __ldg(&esrc[i + 6]);
        int s7 = __ldg(&esrc[i + 7]);
        float4 v0 = __ldg((const float4*)&y[s0 * DIM + lane4]);
        float4 v1 = __ldg((const float4*)&y[s1 * DIM + lane4]);
        float4 v2 = __ldg((const float4*)&y[s2 * DIM + lane4]);
        float4 v3 = __ldg((const float4*)&y[s3 * DIM + lane4]);
        float4 v4 = __ldg((const float4*)&y[s4 * DIM + lane4]);
        float4 v5 = __ldg((const float4*)&y[s5 * DIM + lane4]);
        float4 v6 = __ldg((const float4*)&y[s6 * DIM + lane4]);
        float4 v7 = __ldg((const float4*)&y[s7 * DIM + lane4]);
        a0.x += v0.x; a0.y += v0.y; a0.z += v0.z; a0.w += v0.w;
        a1.x += v1.x; a1.y += v1.y; a1.z += v1.z; a1.w += v1.w;
        a2.x += v2.x; a2.y += v2.y; a2.z += v2.z; a2.w += v2.w;
        a3.x += v3.x; a3.y += v3.y; a3.z += v3.z; a3.w += v3.w;
        a0.x += v4.x; a0.y += v4.y; a0.z += v4.z; a0.w += v4.w;
        a1.x += v5.x; a1.y += v5.y; a1.z += v5.z; a1.w += v5.w;
        a2.x += v6.x; a2.y += v6.y; a2.z += v6.z; a2.w += v6.w;
        a3.x += v7.x; a3.y += v7.y; a3.z += v7.z; a3.w += v7.w;
    }
    for (; i + 2 <= e; i += 2) {
        int s0 = __ldg(&esrc[i + 0]);
        int s1 = __ldg(&esrc[i + 1]);
        float4 v0 = __ldg((const float4*)&y[s0 * DIM + lane4]);
        float4 v1 = __ldg((const float4*)&y[s1 * DIM + lane4]);
        a0.x += v0.x; a0.y += v0.y; a0.z += v0.z; a0.w += v0.w;
        a1.x += v1.x; a1.y += v1.y; a1.z += v1.z; a1.w += v1.w;
    }
    if (i < e) {
        int s0 = __ldg(&esrc[i]);
        float4 v0 = __ldg((const float4*)&y[s0 * DIM + lane4]);
        a2.x += v0.x; a2.y += v0.y; a2.z += v0.z; a2.w += v0.w;
    }
    float4 r;
    r.x = (a0.x + a1.x) + (a2.x + a3.x);
    r.y = (a0.y + a1.y) + (a2.y + a3.y);
    r.z = (a0.z + a1.z) + (a2.z + a3.z);
    r.w = (a0.w + a1.w) + (a2.w + a3.w);
    return r;
}

// Layer-1 aggregation fused with relu + logmap0 AND the layer-2 pre-transform:
// writes xTp (k-pair transposed) directly — no agg buffer, no facT2 kernel.
// 50000 % 8 == 0, so every block is full.
#define GR_PITCH 132
__global__ void __launch_bounds__(256)
gather_xt_kernel(const int* __restrict__ esrc, const int* __restrict__ rs,
                 const float* __restrict__ y, u64* __restrict__ xTp) {
    __shared__ float sRow[8 * GR_PITCH];
    const int tid = threadIdx.x, lane = tid & 31, wid = tid >> 5;
    const int node0 = blockIdx.x * 8;
    const int node = node0 + wid;

    const int s = rs[node];
    const int e = rs[node + 1];
    float4 r = gather_row(esrc, y, s, e, lane * 4);

    r.x = fmaxf(r.x, 0.f); r.y = fmaxf(r.y, 0.f);
    r.z = fmaxf(r.z, 0.f); r.w = fmaxf(r.w, 0.f);

    float ss = r.x * r.x + r.y * r.y + r.z * r.z + r.w * r.w;
    ss += __shfl_xor_sync(0xffffffff, ss, 16);
    ss += __shfl_xor_sync(0xffffffff, ss, 8);
    ss += __shfl_xor_sync(0xffffffff, ss, 4);
    ss += __shfl_xor_sync(0xffffffff, ss, 2);
    ss += __shfl_xor_sync(0xffffffff, ss, 1);
    float n = fmaxf(sqrtf(ss), EPSF);
    float f = atanhf(fminf(n, MAX_NORM)) / n;

    float4 o = make_float4(f * r.x, f * r.y, f * r.z, f * r.w);
    *(float4*)&sRow[wid * GR_PITCH + lane * 4] = o;
    __syncthreads();

    // pack + transposed write: 512 u64 (64 kp x 8 nodes), 2 per thread
#pragma unroll
    for (int q = 0; q < 2; q++) {
        int idx = q * 256 + tid;        // 0..511
        int kp = idx >> 3, nl = idx & 7;
        const float* sr = &sRow[nl * GR_PITCH];
        xTp[kp * XTP + node0 + nl] = pack2(sr[2 * kp], sr[2 * kp + 1]);
    }
}

// Layer-2 aggregation fused with classifier.
__global__ void __launch_bounds__(256)
gather_cls_kernel(const int* __restrict__ esrc, const int* __restrict__ rs,
                  const float* __restrict__ y, const float* __restrict__ Wc,
                  const float* __restrict__ bc, float* __restrict__ out) {
    __shared__ float Wcs[NUM_CLASSES * DIM];
    __shared__ float bcs[NUM_CLASSES];
    const int tid = threadIdx.x;
    for (int i = tid; i < NUM_CLASSES * DIM; i += blockDim.x) Wcs[i] = Wc[i];
    if (tid < NUM_CLASSES) bcs[tid] = bc[tid];
    __syncthreads();

    const int lane = tid & 31;
    const int wid  = tid >> 5;
    const int node = blockIdx.x * (blockDim.x >> 5) + wid;
    if (node >= N_NODES) return;

    const int s = rs[node];
    const int e = rs[node + 1];
    float4 h = gather_row(esrc, y, s, e, lane * 4);

    h.x = fmaxf(h.x, 0.f); h.y = fmaxf(h.y, 0.f);
    h.z = fmaxf(h.z, 0.f); h.w = fmaxf(h.w, 0.f);

    float sq = h.x * h.x + h.y * h.y + h.z * h.z + h.w * h.w;
    sq += __shfl_xor_sync(0xffffffff, sq, 16);
    sq += __shfl_xor_sync(0xffffffff, sq, 8);
    sq += __shfl_xor_sync(0xffffffff, sq, 4);
    sq += __shfl_xor_sync(0xffffffff, sq, 2);
    sq += __shfl_xor_sync(0xffffffff, sq, 1);
    float n = fmaxf(sqrtf(sq), EPSF);
    float f = atanhf(fminf(n, MAX_NORM)) / n;
    float4 t = make_float4(f * h.x, f * h.y, f * h.z, f * h.w);

#pragma unroll
    for (int c = 0; c < NUM_CLASSES; c++) {
        float4 w = *(const float4*)&Wcs[c * DIM + lane * 4];
        float p = t.x * w.x + t.y * w.y + t.z * w.z + t.w * w.w;
        p += __shfl_xor_sync(0xffffffff, p, 16);
        p += __shfl_xor_sync(0xffffffff, p, 8);
        p += __shfl_xor_sync(0xffffffff, p, 4);
        p += __shfl_xor_sync(0xffffffff, p, 2);
        p += __shfl_xor_sync(0xffffffff, p, 1);
        if (lane == 0) out[node * NUM_CLASSES + c] = p + bcs[c];
    }
}

// ---------------------------------------------------------------------------
extern "C" void kernel_launch(void* const* d_in, const int* in_sizes, int n_in,
                              void* d_out, int out_size) {
    const int*   e32 = (const int*)d_in[0];
    const float* x   = (const float*)d_in[1];
    const float* W1  = (const float*)d_in[2];
    const float* b1  = (const float*)d_in[3];
    const float* W2  = (const float*)d_in[4];
    const float* b2  = (const float*)d_in[5];
    const float* Wc  = (const float*)d_in[6];
    const float* bc  = (const float*)d_in[7];
    float* out = (float*)d_out;

    float* y;
    u64 *xTp, *Wp1, *Wp2;
    int *rs, *es;
    cudaGetSymbolAddress((void**)&y,   g_y);
    cudaGetSymbolAddress((void**)&xTp, g_xTp);
    cudaGetSymbolAddress((void**)&Wp1, g_Wp1);
    cudaGetSymbolAddress((void**)&Wp2, g_Wp2);
    cudaGetSymbolAddress((void**)&rs,  g_rowstart);
    cudaGetSymbolAddress((void**)&es,  g_esrc);

    // one-time host resources (no device memory involved)
    static cudaStream_t s2 = nullptr;
    static cudaEvent_t evF = nullptr, evW = nullptr, evC = nullptr;
    static bool init_done = false;
    if (!init_done) {
        init_done = true;
        cudaStreamCreateWithFlags(&s2, cudaStreamNonBlocking);
        cudaEventCreateWithFlags(&evF, cudaEventDisableTiming);
        cudaEventCreateWithFlags(&evW, cudaEventDisableTiming);
        cudaEventCreateWithFlags(&evC, cudaEventDisableTiming);
        cudaFuncSetAttribute(mm_kernel,
                             cudaFuncAttributeMaxDynamicSharedMemorySize, MM_SMEM);
    }

    const int ftblocks = (N_NODES + 31) / 32;   // 1563
    const int gblocks  = N_NODES / 8;           // 6250, exact

    // fork side stream: W prep + CSR build overlap layer-1 transform
    cudaEventRecord(evF, 0);
    cudaStreamWaitEvent(s2, evF, 0);
    wprep_kernel<<<8, 256, 0, s2>>>(W1, W2, Wp1, Wp2);
    cudaEventRecord(evW, s2);
    csr_kernel<<<CSR_BLOCKS, CSR_THREADS, 0, s2>>>(e32);
    cudaEventRecord(evC, s2);

    // main stream
    facT_kernel<<<ftblocks, 256>>>(x, xTp);
    cudaStreamWaitEvent(0, evW, 0);                    // mm1 needs Wp1
    mm_kernel<<<MM_GRID, 256, MM_SMEM>>>(xTp, Wp1, b1, y);
    cudaStreamWaitEvent(0, evC, 0);                    // gather needs CSR
    gather_xt_kernel<<<gblocks, 256>>>(es, rs, y, xTp);  // gather+relu+logmap+transpose
    mm_kernel<<<MM_GRID, 256, MM_SMEM>>>(xTp, Wp2, b2, y);
    gather_cls_kernel<<<gblocks, 256>>>(es, rs, y, Wc, bc, out);
}

// round 16
// speedup vs baseline: 1.3243x; 1.0531x over previous
#include <cuda_runtime.h>
#include <cuda_bf16.h>
#include <math.h>

#define N_NODES 50000
#define N_EDGES 600000
#define DIM 128
#define NUM_CLASSES 10
#define EPSF 1e-15f
#define MAX_NORM (1.0f - 1e-5f)

#define KP 64                      // k-pairs
#define XTP 50048                  // node pitch for pair-packed xT
#define FT_PITCH 129
#define MM_TILES ((N_NODES + 63) / 64)   // 782
#define MM_GRID 296
#define MM_SMEM ((KP * DIM + KP * 64) * 8)   // Wsh 64KB + Tsh 32KB = 96KB

#define CSR_BLOCKS 49
#define CSR_THREADS 1024

typedef unsigned long long u64;

// scratch (device globals: no allocation allowed)
__device__ float g_y[N_NODES * DIM];
__device__ u64   g_xTp[KP * XTP];        // (t[2kp][n], t[2kp+1][n])
__device__ u64   g_Wp1[KP * DIM];        // (W[j][2kp], W[j][2kp+1]) at [kp*128+j]
__device__ u64   g_Wp2[KP * DIM];
__device__ int   g_mult;
__device__ int   g_count[N_NODES];
__device__ int   g_cursor[N_NODES];
__device__ int   g_rowstart[N_NODES + 1];
__device__ int   g_bsum[CSR_BLOCKS];
__device__ volatile unsigned g_bar_gen;   // monotonic across graph replays
__device__ unsigned g_bar_cnt;            // self-resets
__device__ int   g_esrc[N_EDGES];

// ---------------------------------------------------------------------------
// packed fp32x2 helpers (Blackwell FFMA2 — PTX-only)
__device__ __forceinline__ u64 fma2(u64 a, u64 b, u64 c) {
    u64 d;
    asm("fma.rn.f32x2 %0, %1, %2, %3;" : "=l"(d) : "l"(a), "l"(b), "l"(c));
    return d;
}
__device__ __forceinline__ u64 add2(u64 a, u64 b) {
    u64 d;
    asm("add.rn.f32x2 %0, %1, %2;" : "=l"(d) : "l"(a), "l"(b));
    return d;
}
__device__ __forceinline__ u64 pack2(float lo, float hi) {
    u64 r;
    asm("mov.b64 %0, {%1, %2};" : "=l"(r) : "f"(lo), "f"(hi));
    return r;
}
__device__ __forceinline__ void unpack2(u64 v, float& lo, float& hi) {
    asm("mov.b64 {%0, %1}, %2;" : "=f"(lo), "=f"(hi) : "l"(v));
}
__device__ __forceinline__ float sum2(u64 v) {
    float lo, hi;
    unpack2(v, lo, hi);
    return lo + hi;
}

// ---------------------------------------------------------------------------
// software grid barrier (all CSR_BLOCKS resident: 49 << 148 SMs)
__device__ __forceinline__ void grid_barrier() {
    __syncthreads();
    if (threadIdx.x == 0) {
        __threadfence();
        unsigned my = g_bar_gen;
        unsigned a = atomicAdd(&g_bar_cnt, 1);
        if (a == CSR_BLOCKS - 1) {
            g_bar_cnt = 0;
            __threadfence();
            g_bar_gen = my + 1;
        } else {
            while (g_bar_gen == my) __nanosleep(32);
        }
    }
    __syncthreads();
}

// ---------------------------------------------------------------------------
// Fused CSR build (side stream): detect + zero + hist + scan + bucket scatter.
__global__ void __launch_bounds__(CSR_THREADS)
csr_kernel(const int* __restrict__ e32) {
    const int b = blockIdx.x, t = threadIdx.x;
    const int gid = b * CSR_THREADS + t;
    const int nth = CSR_BLOCKS * CSR_THREADS;

    if (b == 0 && t < 32) {
        int v1 = e32[2 * t + 1];
        int bad = __any_sync(0xffffffffu, v1 != 0);
        if (t == 0) g_mult = bad ? 1 : 2;
    }
    if (gid < N_NODES) g_count[gid] = 0;
    grid_barrier();

    const int m = g_mult;
    for (int e = gid; e < N_EDGES; e += nth) {
        int dst = e32[(long long)(N_EDGES + e) * m];
        atomicAdd(&g_count[dst], 1);
    }
    grid_barrier();

    __shared__ int wsum[32];
    __shared__ int part[2];
    const int lane = t & 31, w = t >> 5;
    int v = (gid < N_NODES) ? g_count[gid] : 0;
    int x = v;
#pragma unroll
    for (int d = 1; d < 32; d <<= 1) {
        int y = __shfl_up_sync(0xffffffffu, x, d);
        if (lane >= d) x += y;
    }
    if (lane == 31) wsum[w] = x;
    __syncthreads();
    if (w == 0) {
        int s = wsum[lane];
#pragma unroll
        for (int d = 1; d < 32; d <<= 1) {
            int y = __shfl_up_sync(0xffffffffu, s, d);
            if (lane >= d) s += y;
        }
        wsum[lane] = s;
    }
    __syncthreads();
    int excl = x - v + (w ? wsum[w - 1] : 0);
    if (t == CSR_THREADS - 1) g_bsum[b] = excl + v;
    grid_barrier();

    if (t < 64) {
        int pv = (t < b) ? g_bsum[t] : 0;
#pragma unroll
        for (int d = 16; d > 0; d >>= 1)
            pv += __shfl_xor_sync(0xffffffffu, pv, d);
        if (lane == 0) part[w] = pv;
    }
    __syncthreads();
    const int boff = part[0] + part[1];
    if (gid < N_NODES) {
        int rv = excl + boff;
        g_rowstart[gid] = rv;
        g_cursor[gid] = rv;
    }
    if (gid == 0) g_rowstart[N_NODES] = N_EDGES;
    grid_barrier();

    for (int e = gid; e < N_EDGES; e += nth) {
        int src = e32[(long long)e * m];
        int dst = e32[(long long)(N_EDGES + e) * m];
        int pos = atomicAdd(&g_cursor[dst], 1);
        g_esrc[pos] = src;
    }
}

// ---------------------------------------------------------------------------
// wprep: transpose W1,W2 into k-pair layout Wp[kp*128 + j] = (W[j][2kp], W[j][2kp+1])
__global__ void __launch_bounds__(256)
wprep_kernel(const float* __restrict__ W1, const float* __restrict__ W2,
             u64* __restrict__ Wp1, u64* __restrict__ Wp2) {
    __shared__ float s[32 * FT_PITCH];
    const int mtx = blockIdx.x >> 2;
    const int j0 = (blockIdx.x & 3) * 32;
    const float* W = mtx ? W2 : W1;
    u64* Wp = mtx ? Wp2 : Wp1;
    const int tid = threadIdx.x;

#pragma unroll
    for (int q = 0; q < 4; q++) {
        int idx = q * 256 + tid;          // 0..1023 float4s
        int jj = idx >> 5, k4 = idx & 31;
        float4 v = __ldg((const float4*)&W[(j0 + jj) * DIM + k4 * 4]);
        float* sr = &s[jj * FT_PITCH + k4 * 4];
        sr[0] = v.x; sr[1] = v.y; sr[2] = v.z; sr[3] = v.w;
    }
    __syncthreads();
#pragma unroll
    for (int q = 0; q < 8; q++) {
        int idx = q * 256 + tid;          // 0..2047
        int kp = idx >> 5, jj = idx & 31;
        Wp[kp * DIM + j0 + jj] =
            pack2(s[jj * FT_PITCH + 2 * kp], s[jj * FT_PITCH + 2 * kp + 1]);
    }
}

// ---------------------------------------------------------------------------
// facT: 32-node tile -> logmap0 factor -> k-pair transposed write (layer 1 only).
__global__ void __launch_bounds__(256)
facT_kernel(const float* __restrict__ in, u64* __restrict__ xTp) {
    __shared__ float s[32 * FT_PITCH];
    __shared__ float facs[32];
    const int tid = threadIdx.x, lane = tid & 31, w = tid >> 5;
    const int node0 = blockIdx.x * 32;

#pragma unroll
    for (int q = 0; q < 4; q++) {
        int idx = q * 256 + tid;
        int n = idx >> 5, c4 = idx & 31;
        float4 v = make_float4(0.f, 0.f, 0.f, 0.f);
        if (node0 + n < N_NODES)
            v = __ldg((const float4*)&in[(node0 + n) * DIM + c4 * 4]);
        float* sr = &s[n * FT_PITCH + c4 * 4];
        sr[0] = v.x; sr[1] = v.y; sr[2] = v.z; sr[3] = v.w;
    }
    __syncthreads();

#pragma unroll
    for (int j = 0; j < 4; j++) {
        int n = w * 4 + j;
        const float* sr = &s[n * FT_PITCH];
        float a0 = sr[lane], a1 = sr[lane + 32];
        float a2 = sr[lane + 64], a3 = sr[lane + 96];
        float ss = a0 * a0 + a1 * a1 + a2 * a2 + a3 * a3;
        ss += __shfl_xor_sync(0xffffffff, ss, 16);
        ss += __shfl_xor_sync(0xffffffff, ss, 8);
        ss += __shfl_xor_sync(0xffffffff, ss, 4);
        ss += __shfl_xor_sync(0xffffffff, ss, 2);
        ss += __shfl_xor_sync(0xffffffff, ss, 1);
        if (lane == 0) {
            float nn = fmaxf(sqrtf(ss), EPSF);
            facs[n] = atanhf(fminf(nn, MAX_NORM)) / nn;
        }
    }
    __syncthreads();

    const int n = node0 + lane;
    const bool ok = n < N_NODES;
    const float fl = facs[lane];
#pragma unroll
    for (int i = 0; i < 8; i++) {
        int kp = w + 8 * i;
        float vlo = fl * s[lane * FT_PITCH + 2 * kp];
        float vhi = fl * s[lane * FT_PITCH + 2 * kp + 1];
        if (ok) xTp[kp * XTP + n] = pack2(vlo, vhi);
    }
}

// ---------------------------------------------------------------------------
// mm: y = expmap0( t @ W^T + b ). k-pair packed operands; round-9 proven
// version (unroll-2, ptxas-scheduled; W in smem, conflict-free column map).
__global__ void __launch_bounds__(256, 2)
mm_kernel(const u64* __restrict__ xTp, const u64* __restrict__ Wp,
          const float* __restrict__ bias, float* __restrict__ y) {
    extern __shared__ u64 sm8[];
    u64* Wsh = sm8;                // [kp][j], 64x128
    u64* Tsh = sm8 + KP * DIM;     // [kp][n], 64x64

    const int tid = threadIdx.x, lane = tid & 31, w = tid >> 5;

    {
        const ulonglong2* wg = (const ulonglong2*)Wp;
        ulonglong2* ws = (ulonglong2*)Wsh;
        for (int i = tid; i < KP * DIM / 2; i += 256) ws[i] = wg[i];
    }
    const float b0 = __ldg(&bias[lane]);
    const float b1 = __ldg(&bias[lane + 32]);
    const float b2 = __ldg(&bias[lane + 64]);
    const float b3 = __ldg(&bias[lane + 96]);
    __syncthreads();

    for (int tile = blockIdx.x; tile < MM_TILES; tile += gridDim.x) {
        const int n0 = tile * 64;

        // stage Tsh (coalesced ulonglong2 copies)
#pragma unroll
        for (int q = 0; q < 8; q++) {
            int idx = q * 256 + tid;            // 0..2047 ulonglong2
            int kp = idx >> 5, c2 = idx & 31;
            *(ulonglong2*)&Tsh[kp * 64 + c2 * 2] =
                *(const ulonglong2*)&xTp[kp * XTP + n0 + c2 * 2];
        }
        __syncthreads();

        u64 acc[4][8];
#pragma unroll
        for (int c = 0; c < 4; c++)
#pragma unroll
            for (int p = 0; p < 8; p++) acc[c][p] = 0ULL;

#pragma unroll 2
        for (int kp = 0; kp < KP; kp++) {
            const u64* wrow = &Wsh[kp * DIM + lane];
            u64 w0 = wrow[0];
            u64 w1 = wrow[32];
            u64 w2 = wrow[64];
            u64 w3 = wrow[96];
            const ulonglong2* tp = (const ulonglong2*)&Tsh[kp * 64 + 8 * w];
            ulonglong2 t0 = tp[0], t1 = tp[1], t2 = tp[2], t3 = tp[3];
            acc[0][0] = fma2(w0, t0.x, acc[0][0]);
            acc[1][0] = fma2(w1, t0.x, acc[1][0]);
            acc[2][0] = fma2(w2, t0.x, acc[2][0]);
            acc[3][0] = fma2(w3, t0.x, acc[3][0]);
            acc[0][1] = fma2(w0, t0.y, acc[0][1]);
            acc[1][1] = fma2(w1, t0.y, acc[1][1]);
            acc[2][1] = fma2(w2, t0.y, acc[2][1]);
            acc[3][1] = fma2(w3, t0.y, acc[3][1]);
            acc[0][2] = fma2(w0, t1.x, acc[0][2]);
            acc[1][2] = fma2(w1, t1.x, acc[1][2]);
            acc[2][2] = fma2(w2, t1.x, acc[2][2]);
            acc[3][2] = fma2(w3, t1.x, acc[3][2]);
            acc[0][3] = fma2(w0, t1.y, acc[0][3]);
            acc[1][3] = fma2(w1, t1.y, acc[1][3]);
            acc[2][3] = fma2(w2, t1.y, acc[2][3]);
            acc[3][3] = fma2(w3, t1.y, acc[3][3]);
            acc[0][4] = fma2(w0, t2.x, acc[0][4]);
            acc[1][4] = fma2(w1, t2.x, acc[1][4]);
            acc[2][4] = fma2(w2, t2.x, acc[2][4]);
            acc[3][4] = fma2(w3, t2.x, acc[3][4]);
            acc[0][5] = fma2(w0, t2.y, acc[0][5]);
            acc[1][5] = fma2(w1, t2.y, acc[1][5]);
            acc[2][5] = fma2(w2, t2.y, acc[2][5]);
            acc[3][5] = fma2(w3, t2.y, acc[3][5]);
            acc[0][6] = fma2(w0, t3.x, acc[0][6]);
            acc[1][6] = fma2(w1, t3.x, acc[1][6]);
            acc[2][6] = fma2(w2, t3.x, acc[2][6]);
            acc[3][6] = fma2(w3, t3.x, acc[3][6]);
            acc[0][7] = fma2(w0, t3.y, acc[0][7]);
            acc[1][7] = fma2(w1, t3.y, acc[1][7]);
            acc[2][7] = fma2(w2, t3.y, acc[2][7]);
            acc[3][7] = fma2(w3, t3.y, acc[3][7]);
        }

        // epilogue: collapse k-halves, +bias, expmap0, store (4 coalesced STG.32)
#pragma unroll
        for (int p = 0; p < 8; p++) {
            float h0 = sum2(acc[0][p]) + b0;
            float h1 = sum2(acc[1][p]) + b1;
            float h2 = sum2(acc[2][p]) + b2;
            float h3 = sum2(acc[3][p]) + b3;
            float ss = h0 * h0 + h1 * h1 + h2 * h2 + h3 * h3;
            ss += __shfl_xor_sync(0xffffffff, ss, 16);
            ss += __shfl_xor_sync(0xffffffff, ss, 8);
            ss += __shfl_xor_sync(0xffffffff, ss, 4);
            ss += __shfl_xor_sync(0xffffffff, ss, 2);
            ss += __shfl_xor_sync(0xffffffff, ss, 1);
            float nn = fmaxf(sqrtf(ss), EPSF);
            float f = tanhf(nn) / nn;
            int node = n0 + 8 * w + p;
            if (node < N_NODES) {
                float* yr = &y[node * DIM + lane];
                yr[0]  = f * h0;
                yr[32] = f * h1;
                yr[64] = f * h2;
                yr[96] = f * h3;
            }
        }
        __syncthreads();
    }
}

// ---------------------------------------------------------------------------
// Dual-node CSR gather: two independent idx->row chains per warp, MLP-4 each.
__device__ __forceinline__ void gather_two(const int* __restrict__ esrc,
                                           const float* __restrict__ y,
                                           int iA, int eA, int iB, int eB,
                                           int lane4, float4& outA, float4& outB) {
    float4 aA0 = make_float4(0.f, 0.f, 0.f, 0.f);
    float4 aA1 = make_float4(0.f, 0.f, 0.f, 0.f);
    float4 aB0 = make_float4(0.f, 0.f, 0.f, 0.f);
    float4 aB1 = make_float4(0.f, 0.f, 0.f, 0.f);

    // joint phase: both chains in flight
    while (iA + 4 <= eA && iB + 4 <= eB) {
        int a0 = __ldg(&esrc[iA + 0]);
        int a1 = __ldg(&esrc[iA + 1]);
        int a2 = __ldg(&esrc[iA + 2]);
        int a3 = __ldg(&esrc[iA + 3]);
        int b0 = __ldg(&esrc[iB + 0]);
        int b1 = __ldg(&esrc[iB + 1]);
        int b2 = __ldg(&esrc[iB + 2]);
        int b3 = __ldg(&esrc[iB + 3]);
        float4 vA0 = __ldg((const float4*)&y[a0 * DIM + lane4]);
        float4 vA1 = __ldg((const float4*)&y[a1 * DIM + lane4]);
        float4 vA2 = __ldg((const float4*)&y[a2 * DIM + lane4]);
        float4 vA3 = __ldg((const float4*)&y[a3 * DIM + lane4]);
        float4 vB0 = __ldg((const float4*)&y[b0 * DIM + lane4]);
        float4 vB1 = __ldg((const float4*)&y[b1 * DIM + lane4]);
        float4 vB2 = __ldg((const float4*)&y[b2 * DIM + lane4]);
        float4 vB3 = __ldg((const float4*)&y[b3 * DIM + lane4]);
        aA0.x += vA0.x + vA2.x; aA0.y += vA0.y + vA2.y;
        aA0.z += vA0.z + vA2.z; aA0.w += vA0.w + vA2.w;
        aA1.x += vA1.x + vA3.x; aA1.y += vA1.y + vA3.y;
        aA1.z += vA1.z + vA3.z; aA1.w += vA1.w + vA3.w;
        aB0.x += vB0.x + vB2.x; aB0.y += vB0.y + vB2.y;
        aB0.z += vB0.z + vB2.z; aB0.w += vB0.w + vB2.w;
        aB1.x += vB1.x + vB3.x; aB1.y += vB1.y + vB3.y;
        aB1.z += vB1.z + vB3.z; aB1.w += vB1.w + vB3.w;
        iA += 4; iB += 4;
    }
    // drain A (MLP-4 then singles)
    for (; iA + 4 <= eA; iA += 4) {
        int a0 = __ldg(&esrc[iA + 0]);
        int a1 = __ldg(&esrc[iA + 1]);
        int a2 = __ldg(&esrc[iA + 2]);
        int a3 = __ldg(&esrc[iA + 3]);
        float4 v0 = __ldg((const float4*)&y[a0 * DIM + lane4]);
        float4 v1 = __ldg((const float4*)&y[a1 * DIM + lane4]);
        float4 v2 = __ldg((const float4*)&y[a2 * DIM + lane4]);
        float4 v3 = __ldg((const float4*)&y[a3 * DIM + lane4]);
        aA0.x += v0.x + v2.x; aA0.y += v0.y + v2.y;
        aA0.z += v0.z + v2.z; aA0.w += v0.w + v2.w;
        aA1.x += v1.x + v3.x; aA1.y += v1.y + v3.y;
        aA1.z += v1.z + v3.z; aA1.w += v1.w + v3.w;
    }
    for (; iA + 2 <= eA; iA += 2) {
        int a0 = __ldg(&esrc[iA + 0]);
        int a1 = __ldg(&esrc[iA + 1]);
        float4 v0 = __ldg((const float4*)&y[a0 * DIM + lane4]);
        float4 v1 = __ldg((const float4*)&y[a1 * DIM + lane4]);
        aA0.x += v0.x; aA0.y += v0.y; aA0.z += v0.z; aA0.w += v0.w;
        aA1.x += v1.x; aA1.y += v1.y; aA1.z += v1.z; aA1.w += v1.w;
    }
    if (iA < eA) {
        int a0 = __ldg(&esrc[iA]);
        float4 v0 = __ldg((const float4*)&y[a0 * DIM + lane4]);
        aA0.x += v0.x; aA0.y += v0.y; aA0.z += v0.z; aA0.w += v0.w;
    }
    // drain B
    for (; iB + 4 <= eB; iB += 4) {
        int b0 = __ldg(&esrc[iB + 0]);
        int b1 = __ldg(&esrc[iB + 1]);
        int b2 = __ldg(&esrc[iB + 2]);
        int b3 = __ldg(&esrc[iB + 3]);
        float4 v0 = __ldg((const float4*)&y[b0 * DIM + lane4]);
        float4 v1 = __ldg((const float4*)&y[b1 * DIM + lane4]);
        float4 v2 = __ldg((const float4*)&y[b2 * DIM + lane4]);
        float4 v3 = __ldg((const float4*)&y[b3 * DIM + lane4]);
        aB0.x += v0.x + v2.x; aB0.y += v0.y + v2.y;
        aB0.z += v0.z + v2.z; aB0.w += v0.w + v2.w;
        aB1.x += v1.x + v3.x; aB1.y += v1.y + v3.y;
        aB1.z += v1.z + v3.z; aB1.w += v1.w + v3.w;
    }
    for (; iB + 2 <= eB; iB += 2) {
        int b0 = __ldg(&esrc[iB + 0]);
        int b1 = __ldg(&esrc[iB + 1]);
        float4 v0 = __ldg((const float4*)&y[b0 * DIM + lane4]);
        float4 v1 = __ldg((const float4*)&y[b1 * DIM + lane4]);
        aB0.x += v0.x; aB0.y += v0.y; aB0.z += v0.z; aB0.w += v0.w;
        aB1.x += v1.x; aB1.y += v1.y; aB1.z += v1.z; aB1.w += v1.w;
    }
    if (iB < eB) {
        int b0 = __ldg(&esrc[iB]);
        float4 v0 = __ldg((const float4*)&y[b0 * DIM + lane4]);
        aB0.x += v0.x; aB0.y += v0.y; aB0.z += v0.z; aB0.w += v0.w;
    }

    outA.x = aA0.x + aA1.x; outA.y = aA0.y + aA1.y;
    outA.z = aA0.z + aA1.z; outA.w = aA0.w + aA1.w;
    outB.x = aB0.x + aB1.x; outB.y = aB0.y + aB1.y;
    outB.z = aB0.z + aB1.z; outB.w = aB0.w + aB1.w;
}

__device__ __forceinline__ float4 relu4(float4 v) {
    return make_float4(fmaxf(v.x, 0.f), fmaxf(v.y, 0.f),
                       fmaxf(v.z, 0.f), fmaxf(v.w, 0.f));
}

// packed dual-node warp reduction: (sumA, sumB) in one 5-shfl chain
__device__ __forceinline__ u64 wreduce2(u64 v) {
#pragma unroll
    for (int d = 16; d > 0; d >>= 1)
        v = add2(v, __shfl_xor_sync(0xffffffffu, v, d));
    return v;
}

// Layer-1 aggregation fused with relu + logmap0 + layer-2 pre-transform.
// Warp handles 2 nodes (interleaved chains); block = 16 nodes; 50000%16==0.
#define GR_PITCH 132
__global__ void __launch_bounds__(256)
gather_xt_kernel(const int* __restrict__ esrc, const int* __restrict__ rs,
                 const float* __restrict__ y, u64* __restrict__ xTp) {
    __shared__ float sRow[16 * GR_PITCH];
    const int tid = threadIdx.x, lane = tid & 31, wid = tid >> 5;
    const int node0 = blockIdx.x * 16;
    const int nA = node0 + 2 * wid;

    const int sA = rs[nA];
    const int sB = rs[nA + 1];
    const int eB = rs[nA + 2];
    float4 rA, rB;
    gather_two(esrc, y, sA, sB, sB, eB, lane * 4, rA, rB);
    rA = relu4(rA);
    rB = relu4(rB);

    float ssA = rA.x * rA.x + rA.y * rA.y + rA.z * rA.z + rA.w * rA.w;
    float ssB = rB.x * rB.x + rB.y * rB.y + rB.z * rB.z + rB.w * rB.w;
    u64 ssp = wreduce2(pack2(ssA, ssB));
    unpack2(ssp, ssA, ssB);
    float nnA = fmaxf(sqrtf(ssA), EPSF);
    float nnB = fmaxf(sqrtf(ssB), EPSF);
    float fA = atanhf(fminf(nnA, MAX_NORM)) / nnA;
    float fB = atanhf(fminf(nnB, MAX_NORM)) / nnB;

    float4 oA = make_float4(fA * rA.x, fA * rA.y, fA * rA.z, fA * rA.w);
    float4 oB = make_float4(fB * rB.x, fB * rB.y, fB * rB.z, fB * rB.w);
    *(float4*)&sRow[(2 * wid) * GR_PITCH + lane * 4] = oA;
    *(float4*)&sRow[(2 * wid + 1) * GR_PITCH + lane * 4] = oB;
    __syncthreads();

    // pack + transposed write: 64 kp x 16 nodes = 1024 u64, 4 per thread
#pragma unroll
    for (int q = 0; q < 4; q++) {
        int idx = q * 256 + tid;        // 0..1023
        int kp = idx >> 4, nl = idx & 15;
        const float* sr = &sRow[nl * GR_PITCH];
        xTp[kp * XTP + node0 + nl] = pack2(sr[2 * kp], sr[2 * kp + 1]);
    }
}

// Layer-2 aggregation fused with classifier; 2 nodes per warp.
__global__ void __launch_bounds__(256)
gather_cls_kernel(const int* __restrict__ esrc, const int* __restrict__ rs,
                  const float* __restrict__ y, const float* __restrict__ Wc,
                  const float* __restrict__ bc, float* __restrict__ out) {
    __shared__ float Wcs[NUM_CLASSES * DIM];
    __shared__ float bcs[NUM_CLASSES];
    const int tid = threadIdx.x;
    for (int i = tid; i < NUM_CLASSES * DIM; i += blockDim.x) Wcs[i] = Wc[i];
    if (tid < NUM_CLASSES) bcs[tid] = bc[tid];
    __syncthreads();

    const int lane = tid & 31;
    const int wid  = tid >> 5;
    const int nA = blockIdx.x * 16 + 2 * wid;

    const int sA = rs[nA];
    const int sB = rs[nA + 1];
    const int eB = rs[nA + 2];
    float4 hA, hB;
    gather_two(esrc, y, sA, sB, sB, eB, lane * 4, hA, hB);
    hA = relu4(hA);
    hB = relu4(hB);

    float sqA = hA.x * hA.x + hA.y * hA.y + hA.z * hA.z + hA.w * hA.w;
    float sqB = hB.x * hB.x + hB.y * hB.y + hB.z * hB.z + hB.w * hB.w;
    u64 sp = wreduce2(pack2(sqA, sqB));
    unpack2(sp, sqA, sqB);
    float nnA = fmaxf(sqrtf(sqA), EPSF);
    float nnB = fmaxf(sqrtf(sqB), EPSF);
    float fA = atanhf(fminf(nnA, MAX_NORM)) / nnA;
    float fB = atanhf(fminf(nnB, MAX_NORM)) / nnB;
    float4 tA = make_float4(fA * hA.x, fA * hA.y, fA * hA.z, fA * hA.w);
    float4 tB = make_float4(fB * hB.x, fB * hB.y, fB * hB.z, fB * hB.w);

#pragma unroll
    for (int c = 0; c < NUM_CLASSES; c++) {
        float4 w = *(const float4*)&Wcs[c * DIM + lane * 4];
        float pA = tA.x * w.x + tA.y * w.y + tA.z * w.z + tA.w * w.w;
        float pB = tB.x * w.x + tB.y * w.y + tB.z * w.z + tB.w * w.w;
        u64 pp = wreduce2(pack2(pA, pB));
        if (lane == 0) {
            float qa, qb;
            unpack2(pp, qa, qb);
            out[nA * NUM_CLASSES + c] = qa + bcs[c];
            out[(nA + 1) * NUM_CLASSES + c] = qb + bcs[c];
        }
    }
}

// ---------------------------------------------------------------------------
extern "C" void kernel_launch(void* const* d_in, const int* in_sizes, int n_in,
                              void* d_out, int out_size) {
    const int*   e32 = (const int*)d_in[0];
    const float* x   = (const float*)d_in[1];
    const float* W1  = (const float*)d_in[2];
    const float* b1  = (const float*)d_in[3];
    const float* W2  = (const float*)d_in[4];
    const float* b2  = (const float*)d_in[5];
    const float* Wc  = (const float*)d_in[6];
    const float* bc  = (const float*)d_in[7];
    float* out = (float*)d_out;

    float* y;
    u64 *xTp, *Wp1, *Wp2;
    int *rs, *es;
    cudaGetSymbolAddress((void**)&y,   g_y);
    cudaGetSymbolAddress((void**)&xTp, g_xTp);
    cudaGetSymbolAddress((void**)&Wp1, g_Wp1);
    cudaGetSymbolAddress((void**)&Wp2, g_Wp2);
    cudaGetSymbolAddress((void**)&rs,  g_rowstart);
    cudaGetSymbolAddress((void**)&es,  g_esrc);

    // one-time host resources (no device memory involved)
    static cudaStream_t s2 = nullptr;
    static cudaEvent_t evF = nullptr, evW = nullptr, evC = nullptr;
    static bool init_done = false;
    if (!init_done) {
        init_done = true;
        cudaStreamCreateWithFlags(&s2, cudaStreamNonBlocking);
        cudaEventCreateWithFlags(&evF, cudaEventDisableTiming);
        cudaEventCreateWithFlags(&evW, cudaEventDisableTiming);
        cudaEventCreateWithFlags(&evC, cudaEventDisableTiming);
        cudaFuncSetAttribute(mm_kernel,
                             cudaFuncAttributeMaxDynamicSharedMemorySize, MM_SMEM);
    }

    const int ftblocks = (N_NODES + 31) / 32;   // 1563
    const int gblocks  = N_NODES / 16;          // 3125, exact

    // fork side stream: W prep + CSR build overlap layer-1 transform
    cudaEventRecord(evF, 0);
    cudaStreamWaitEvent(s2, evF, 0);
    wprep_kernel<<<8, 256, 0, s2>>>(W1, W2, Wp1, Wp2);
    cudaEventRecord(evW, s2);
    csr_kernel<<<CSR_BLOCKS, CSR_THREADS, 0, s2>>>(e32);
    cudaEventRecord(evC, s2);

    // main stream
    facT_kernel<<<ftblocks, 256>>>(x, xTp);
    cudaStreamWaitEvent(0, evW, 0);                    // mm1 needs Wp1
    mm_kernel<<<MM_GRID, 256, MM_SMEM>>>(xTp, Wp1, b1, y);
    cudaStreamWaitEvent(0, evC, 0);                    // gather needs CSR
    gather_xt_kernel<<<gblocks, 256>>>(es, rs, y, xTp);  // gather+relu+logmap+transpose
    mm_kernel<<<MM_GRID, 256, MM_SMEM>>>(xTp, Wp2, b2, y);
    gather_cls_kernel<<<gblocks, 256>>>(es, rs, y, Wc, bc, out);
}